// round 9
// baseline (speedup 1.0000x reference)
#include <cuda_runtime.h>
#include <cuda_bf16.h>
#include <cstdint>

#define NTOK 32768
#define NEXP 64
#define CDIM 1024
#define CAPV 2048

#define BM 128
#define BK 16
#define NCH (CDIM / BK)     // 64 chunks
#define THREADS 256

// smem stage layout (bytes): A 128 rows x 80B (16 fp32 + pad), B 16 rows x 272B
#define A_STRIDE_B 80
#define A_STRIDE_W 20
#define B_STRIDE_B 272
#define B_STRIDE_W 68
#define A_BYTES (128 * A_STRIDE_B)               // 10240
#define STAGE_BYTES (A_BYTES + BK * B_STRIDE_B)  // 14592
#define NSTAGE 4
#define SMEM_TOTAL (NSTAGE * STAGE_BYTES)        // 58368

__device__ int   g_top[2 * NTOK];
__device__ __align__(16) float g_wT[CDIM * NEXP];   // wT[k][e]

typedef unsigned long long u64;

// ---------------------------------------------------------------------------
// helpers
// ---------------------------------------------------------------------------
__device__ __forceinline__ uint32_t smem_u32(const void* p) {
    uint32_t a;
    asm("{ .reg .u64 t; cvta.to.shared.u64 t, %1; cvt.u32.u64 %0, t; }" : "=r"(a) : "l"(p));
    return a;
}
__device__ __forceinline__ u64 pack2(float lo, float hi) {
    u64 r;
    asm("mov.b64 %0, {%1, %2};" : "=l"(r)
        : "r"(__float_as_uint(lo)), "r"(__float_as_uint(hi)));
    return r;
}
__device__ __forceinline__ void fma2(u64& d, u64 a, u64 b) {
    asm("fma.rn.f32x2 %0, %1, %2, %0;" : "+l"(d) : "l"(a), "l"(b));
}
__device__ __forceinline__ void unpack2(u64 v, float& lo, float& hi) {
    uint32_t l, h;
    asm("mov.b64 {%0, %1}, %2;" : "=r"(l), "=r"(h) : "l"(v));
    lo = __uint_as_float(l);
    hi = __uint_as_float(h);
}
__device__ __forceinline__ void cp16(uint32_t s, const void* g) {
    asm volatile("cp.async.cg.shared.global [%0], [%1], 16;" :: "r"(s), "l"(g));
}
#define CP_COMMIT() asm volatile("cp.async.commit_group;" ::: "memory")
#define CP_WAIT2()  asm volatile("cp.async.wait_group 2;" ::: "memory")

// ---------------------------------------------------------------------------
// Kernel 0: transpose w[64][1024] -> g_wT[1024][64]
// ---------------------------------------------------------------------------
__global__ __launch_bounds__(256) void wtrans_kernel(const float* __restrict__ w)
{
    int t = blockIdx.x * 256 + threadIdx.x;   // 65536 total
    int e = t >> 10, k = t & 1023;
    g_wT[k * 64 + e] = w[e * 1024 + k];
}

// ---------------------------------------------------------------------------
// Kernel 1: fused FFMA2 GEMM (M=32768,N=64,K=1024) + top-2 + softmax.
// 256 threads: ty=tid>>3 (rows m = ty + 32*r), tx=tid&7 (experts tx*8..+7).
// 4-stage cp.async pipeline.
// ---------------------------------------------------------------------------
__global__ __launch_bounds__(THREADS) void gemm_top2_kernel(
    const float* __restrict__ x,
    float* __restrict__ out_probs, float* __restrict__ out_idx)
{
    extern __shared__ char smem[];
    const uint32_t sb = smem_u32(smem);

    const int tid  = threadIdx.x;
    const int ty   = tid >> 3;
    const int tx   = tid & 7;
    const int row0 = blockIdx.x * BM;

    auto issue = [&](int c) {
        const uint32_t st = sb + (c & 3) * STAGE_BYTES;
        // A: 128 rows x 16 fp32 -> 512 x 16B chunks, 2 per thread
        int id = tid;
        int m = id >> 2, q = id & 3;
        cp16(st + m * A_STRIDE_B + q * 16,
             x + (size_t)(row0 + m) * CDIM + c * BK + q * 4);
        id = tid + 256;
        m = id >> 2; q = id & 3;
        cp16(st + m * A_STRIDE_B + q * 16,
             x + (size_t)(row0 + m) * CDIM + c * BK + q * 4);
        // B: 16 k-rows x 64 fp32 -> 256 x 16B chunks, 1 per thread
        int kk = tid >> 4, ch = tid & 15;
        cp16(st + A_BYTES + kk * B_STRIDE_B + ch * 16,
             g_wT + (c * BK + kk) * 64 + ch * 4);
    };

    u64 acc[4][4];
#pragma unroll
    for (int r = 0; r < 4; r++)
#pragma unroll
        for (int q = 0; q < 4; q++) acc[r][q] = 0ull;

    issue(0); CP_COMMIT();
    issue(1); CP_COMMIT();
    issue(2); CP_COMMIT();

#pragma unroll 1
    for (int c = 0; c < NCH; c++) {
        CP_WAIT2();
        __syncthreads();
        if (c + 3 < NCH) issue(c + 3);
        CP_COMMIT();

        const float* A = reinterpret_cast<const float*>(smem + (c & 3) * STAGE_BYTES);
        const float* B = reinterpret_cast<const float*>(smem + (c & 3) * STAGE_BYTES + A_BYTES);

#pragma unroll
        for (int k4 = 0; k4 < BK; k4 += 4) {
            float a[4][4];
#pragma unroll
            for (int r = 0; r < 4; r++) {
                float4 v = *reinterpret_cast<const float4*>(
                    A + (ty + 32 * r) * A_STRIDE_W + k4);
                a[r][0] = v.x; a[r][1] = v.y; a[r][2] = v.z; a[r][3] = v.w;
            }
#pragma unroll
            for (int kk = 0; kk < 4; kk++) {
                const int k = k4 + kk;
                float4 b0 = *reinterpret_cast<const float4*>(B + k * B_STRIDE_W + tx * 8);
                float4 b1 = *reinterpret_cast<const float4*>(B + k * B_STRIDE_W + tx * 8 + 4);
                u64 bv0 = pack2(b0.x, b0.y);
                u64 bv1 = pack2(b0.z, b0.w);
                u64 bv2 = pack2(b1.x, b1.y);
                u64 bv3 = pack2(b1.z, b1.w);
#pragma unroll
                for (int r = 0; r < 4; r++) {
                    u64 av = pack2(a[r][kk], a[r][kk]);
                    fma2(acc[r][0], av, bv0);
                    fma2(acc[r][1], av, bv1);
                    fma2(acc[r][2], av, bv2);
                    fma2(acc[r][3], av, bv3);
                }
            }
        }
    }

    // --- epilogue: per-row top-2 over 64 experts, merged across tx group ---
#pragma unroll
    for (int r = 0; r < 4; r++) {
        float v[8];
#pragma unroll
        for (int q = 0; q < 4; q++) unpack2(acc[r][q], v[2 * q], v[2 * q + 1]);

        float a1 = v[0], a2 = -3.4e38f;
        int j1 = tx * 8, j2 = tx * 8;
#pragma unroll
        for (int j = 1; j < 8; j++) {
            float vv = v[j];
            int jj = tx * 8 + j;
            if (vv > a1)      { a2 = a1; j2 = j1; a1 = vv; j1 = jj; }
            else if (vv > a2) { a2 = vv; j2 = jj; }
        }
#pragma unroll
        for (int o = 4; o > 0; o >>= 1) {
            float b1 = __shfl_down_sync(0xffffffffu, a1, o, 8);
            int   k1 = __shfl_down_sync(0xffffffffu, j1, o, 8);
            float b2 = __shfl_down_sync(0xffffffffu, a2, o, 8);
            int   k2 = __shfl_down_sync(0xffffffffu, j2, o, 8);
            bool first = (a1 > b1) || (a1 == b1 && j1 < k1);
            if (first) {
                bool s = (a2 > b1) || (a2 == b1 && j2 < k1);
                if (!s) { a2 = b1; j2 = k1; }
            } else {
                bool s = (b2 > a1) || (b2 == a1 && k2 < j1);
                if (s) { a1 = b1; j1 = k1; a2 = b2; j2 = k2; }
                else   { a2 = a1; j2 = j1; a1 = b1; j1 = k1; }
            }
        }
        if (tx == 0) {
            int t = row0 + ty + 32 * r;
            float ed = __expf(a2 - a1);
            float p1 = 1.0f / (1.0f + ed);
            float p2 = ed / (1.0f + ed);
            g_top[t]        = j1;
            g_top[NTOK + t] = j2;
            out_probs[2 * t]     = p1;
            out_probs[2 * t + 1] = p2;
            out_idx[2 * t]       = (float)j1;
            out_idx[2 * t + 1]   = (float)j2;
        }
    }
}

// ---------------------------------------------------------------------------
// Kernel 2: rank/capacity. 128 CTAs: bid>>1 = expert, bid&1 = stream.
// Stream-1 CTAs first count stream-0 matches (carry), then scan their stream.
// ---------------------------------------------------------------------------
__global__ __launch_bounds__(1024) void rank_kernel(
    float* __restrict__ out_mask, float* __restrict__ out_probs,
    float* __restrict__ out_rank)
{
    const int e    = blockIdx.x >> 1;
    const int s    = blockIdx.x & 1;
    const int tid  = threadIdx.x;
    const int lane = tid & 31;
    const int wid  = tid >> 5;

    __shared__ int wsum[32];
    __shared__ int stotal;

    int carry = 0;
    if (s == 1) {
        const int4* p0 = reinterpret_cast<const int4*>(g_top);
        int cnt = 0;
#pragma unroll
        for (int i = 0; i < 8; i++) {
            int4 v = p0[i * 1024 + tid];
            cnt += (v.x == e) + (v.y == e) + (v.z == e) + (v.w == e);
        }
#pragma unroll
        for (int o = 16; o > 0; o >>= 1) cnt += __shfl_down_sync(0xffffffffu, cnt, o);
        if (lane == 0) wsum[wid] = cnt;
        __syncthreads();
        if (tid < 32) {
            int c2 = wsum[lane];
#pragma unroll
            for (int o = 16; o > 0; o >>= 1) c2 += __shfl_down_sync(0xffffffffu, c2, o);
            if (lane == 0) stotal = c2;
        }
        __syncthreads();
        carry = stotal;
    }

    const int4* p = reinterpret_cast<const int4*>(g_top + s * NTOK);
#pragma unroll 1
    for (int c = 0; c < NTOK / 4096; c++) {
        int4 v = p[c * 1024 + tid];
        int m0 = (v.x == e), m1 = (v.y == e), m2 = (v.z == e), m3 = (v.w == e);
        int cs = m0 + m1 + m2 + m3;

        int inc = cs;
#pragma unroll
        for (int o = 1; o < 32; o <<= 1) {
            int t2 = __shfl_up_sync(0xffffffffu, inc, o);
            if (lane >= o) inc += t2;
        }
        if (lane == 31) wsum[wid] = inc;
        __syncthreads();
        if (wid == 0) {
            int wv = wsum[lane];
            int winc = wv;
#pragma unroll
            for (int o = 1; o < 32; o <<= 1) {
                int t2 = __shfl_up_sync(0xffffffffu, winc, o);
                if (lane >= o) winc += t2;
            }
            wsum[lane] = winc - wv;
            if (lane == 31) stotal = winc;
        }
        __syncthreads();

        int r  = carry + wsum[wid] + (inc - cs);
        int i0 = (c * 1024 + tid) * 4;

        if (m0) {
            int oi = (i0 + 0) * 2 + s;
            out_rank[oi] = (float)r;
            if (r < CAPV) out_mask[(size_t)oi * NEXP + e] = 1.0f;
            else out_probs[oi] = 0.0f;
            r++;
        }
        if (m1) {
            int oi = (i0 + 1) * 2 + s;
            out_rank[oi] = (float)r;
            if (r < CAPV) out_mask[(size_t)oi * NEXP + e] = 1.0f;
            else out_probs[oi] = 0.0f;
            r++;
        }
        if (m2) {
            int oi = (i0 + 2) * 2 + s;
            out_rank[oi] = (float)r;
            if (r < CAPV) out_mask[(size_t)oi * NEXP + e] = 1.0f;
            else out_probs[oi] = 0.0f;
            r++;
        }
        if (m3) {
            int oi = (i0 + 3) * 2 + s;
            out_rank[oi] = (float)r;
            if (r < CAPV) out_mask[(size_t)oi * NEXP + e] = 1.0f;
            else out_probs[oi] = 0.0f;
            r++;
        }
        carry += stotal;
        __syncthreads();
    }
}

// ---------------------------------------------------------------------------
extern "C" void kernel_launch(void* const* d_in, const int* in_sizes, int n_in,
                              void* d_out, int out_size)
{
    const float* x = (const float*)d_in[0];
    const float* w = (const float*)d_in[1];

    float* out       = (float*)d_out;
    float* out_mask  = out;                                   // N*2*64
    float* out_probs = out + (size_t)NTOK * 2 * NEXP;         // N*2
    float* out_idx   = out_probs + NTOK * 2;                  // N*2
    float* out_rank  = out_idx + NTOK * 2;                    // N*2

    cudaFuncSetAttribute(gemm_top2_kernel,
                         cudaFuncAttributeMaxDynamicSharedMemorySize, SMEM_TOTAL);

    wtrans_kernel<<<(NEXP * CDIM) / 256, 256>>>(w);   // 256 blocks
    cudaMemsetAsync(out_mask, 0, (size_t)NTOK * 2 * NEXP * sizeof(float));
    gemm_top2_kernel<<<NTOK / BM, THREADS, SMEM_TOTAL>>>(x, out_probs, out_idx);
    rank_kernel<<<2 * NEXP, 1024>>>(out_mask, out_probs, out_rank);
}

// round 12
// speedup vs baseline: 1.1844x; 1.1844x over previous
#include <cuda_runtime.h>
#include <cuda_bf16.h>
#include <cstdint>

#define NTOK 32768
#define NEXP 64
#define CDIM 1024
#define CAPV 2048

#define BM 128
#define BK 16
#define NCH (CDIM / BK)     // 64 chunks
#define THREADS 256

// smem stage (fp32 words): A k-major [16][132], B k-major [16][72]
#define ASTR 132
#define BSTR 72
#define A_WORDS (BK * ASTR)            // 2112
#define STAGE_W (A_WORDS + BK * BSTR)  // 2112 + 1152 = 3264 words (13056 B)

__device__ int g_top[2 * NTOK];

typedef unsigned long long u64;

// ---------------------------------------------------------------------------
__device__ __forceinline__ u64 pack2(float lo, float hi) {
    u64 r;
    asm("mov.b64 %0, {%1, %2};" : "=l"(r)
        : "r"(__float_as_uint(lo)), "r"(__float_as_uint(hi)));
    return r;
}
__device__ __forceinline__ void fma2(u64& d, u64 a, u64 b) {
    asm("fma.rn.f32x2 %0, %1, %2, %0;" : "+l"(d) : "l"(a), "l"(b));
}
__device__ __forceinline__ void unpack2(u64 v, float& lo, float& hi) {
    uint32_t l, h;
    asm("mov.b64 {%0, %1}, %2;" : "=r"(l), "=r"(h) : "l"(v));
    lo = __uint_as_float(l);
    hi = __uint_as_float(h);
}

// ---------------------------------------------------------------------------
// Kernel 1: fused FFMA2 GEMM (M=32768,N=64,K=1024) + top-2 + softmax.
// 8 warps. warp -> experts wid*8..wid*8+7 ; lane -> rows 4*lane..4*lane+3.
// B smem loads are warp-uniform (broadcast). A is k-major in smem.
// Double-buffered smem fed by register prefetch (distance 2).
// ---------------------------------------------------------------------------
__global__ __launch_bounds__(THREADS) void gemm_top2_kernel(
    const float* __restrict__ x, const float* __restrict__ w,
    float* __restrict__ out_probs, float* __restrict__ out_idx)
{
    __shared__ float sm[2 * STAGE_W];

    const int tid  = threadIdx.x;
    const int wid  = tid >> 5;
    const int lane = tid & 31;
    const int row0 = blockIdx.x * BM;

    // LDG mappings
    const int am = tid & 127;          // A: token row
    const int ak = (tid >> 7) * 8;     // A: k offset within chunk (0 or 8)
    const int be = tid >> 2;           // B: expert 0..63
    const int bk = (tid & 3) * 4;      // B: k offset within chunk {0,4,8,12}

    const float* xrow = x + (size_t)(row0 + am) * CDIM + ak;
    const float* wrow = w + (size_t)be * CDIM + bk;

    float4 rA0, rA1, rB;

    auto ldg = [&](int c) {
        const float* pa = xrow + c * BK;
        rA0 = *reinterpret_cast<const float4*>(pa);
        rA1 = *reinterpret_cast<const float4*>(pa + 4);
        rB  = *reinterpret_cast<const float4*>(wrow + c * BK);
    };
    auto sts = [&](int s) {
        float* st = sm + s * STAGE_W;
        st[(ak + 0) * ASTR + am] = rA0.x;
        st[(ak + 1) * ASTR + am] = rA0.y;
        st[(ak + 2) * ASTR + am] = rA0.z;
        st[(ak + 3) * ASTR + am] = rA0.w;
        st[(ak + 4) * ASTR + am] = rA1.x;
        st[(ak + 5) * ASTR + am] = rA1.y;
        st[(ak + 6) * ASTR + am] = rA1.z;
        st[(ak + 7) * ASTR + am] = rA1.w;
        float* bt = st + A_WORDS;
        bt[(bk + 0) * BSTR + be] = rB.x;
        bt[(bk + 1) * BSTR + be] = rB.y;
        bt[(bk + 2) * BSTR + be] = rB.z;
        bt[(bk + 3) * BSTR + be] = rB.w;
    };

    u64 acc[4][4];
#pragma unroll
    for (int r = 0; r < 4; r++)
#pragma unroll
        for (int q = 0; q < 4; q++) acc[r][q] = 0ull;

    // prologue: stage0 <- chunk0 ; regs <- chunk1
    ldg(0);
    sts(0);
    ldg(1);

#pragma unroll 1
    for (int c = 0; c < NCH; c++) {
        if (c + 1 < NCH) sts((c + 1) & 1);          // regs hold chunk c+1
        if (c + 2 < NCH) ldg(c + 2);
        __syncthreads();                             // publish stage[c&1] (and c+1)

        const float* st = sm + (c & 1) * STAGE_W;
        const float* bt = st + A_WORDS + wid * 8;

#pragma unroll
        for (int k = 0; k < BK; k++) {
            float4 a  = *reinterpret_cast<const float4*>(st + k * ASTR + 4 * lane);
            float4 b0 = *reinterpret_cast<const float4*>(bt + k * BSTR);
            float4 b1 = *reinterpret_cast<const float4*>(bt + k * BSTR + 4);
            u64 bv0 = pack2(b0.x, b0.y);
            u64 bv1 = pack2(b0.z, b0.w);
            u64 bv2 = pack2(b1.x, b1.y);
            u64 bv3 = pack2(b1.z, b1.w);
            u64 av0 = pack2(a.x, a.x);
            u64 av1 = pack2(a.y, a.y);
            u64 av2 = pack2(a.z, a.z);
            u64 av3 = pack2(a.w, a.w);
            fma2(acc[0][0], av0, bv0); fma2(acc[0][1], av0, bv1);
            fma2(acc[0][2], av0, bv2); fma2(acc[0][3], av0, bv3);
            fma2(acc[1][0], av1, bv0); fma2(acc[1][1], av1, bv1);
            fma2(acc[1][2], av1, bv2); fma2(acc[1][3], av1, bv3);
            fma2(acc[2][0], av2, bv0); fma2(acc[2][1], av2, bv1);
            fma2(acc[2][2], av2, bv2); fma2(acc[2][3], av2, bv3);
            fma2(acc[3][0], av3, bv0); fma2(acc[3][1], av3, bv1);
            fma2(acc[3][2], av3, bv2); fma2(acc[3][3], av3, bv3);
        }
        __syncthreads();                             // all done reading stage[c&1]
    }

    // --- per-warp local top-2 (experts wid*8..+7), ascending-index ties ---
    // cand layout in sm (reused): float4 at slot (row*9 + wid)
#pragma unroll
    for (int r = 0; r < 4; r++) {
        float v[8];
#pragma unroll
        for (int q = 0; q < 4; q++) unpack2(acc[r][q], v[2 * q], v[2 * q + 1]);
        float a1 = v[0], a2 = -3.4e38f;
        int j1 = wid * 8, j2 = wid * 8;
#pragma unroll
        for (int j = 1; j < 8; j++) {
            float vv = v[j];
            int jj = wid * 8 + j;
            if (vv > a1)      { a2 = a1; j2 = j1; a1 = vv; j1 = jj; }
            else if (vv > a2) { a2 = vv; j2 = jj; }
        }
        int row = 4 * lane + r;
        float4 cand = make_float4(a1, a2, __int_as_float(j1), __int_as_float(j2));
        *reinterpret_cast<float4*>(sm + (size_t)(row * 9 + wid) * 4) = cand;
    }
    __syncthreads();

    // --- merge 8 warp candidates per row; threads 0..127, one row each ---
    if (tid < BM) {
        const float4* cbase = reinterpret_cast<const float4*>(sm) + tid * 9;
        float4 c0 = cbase[0];
        float best1 = c0.x, best2 = c0.y;
        int   j1 = __float_as_int(c0.z), j2 = __float_as_int(c0.w);
#pragma unroll
        for (int wv = 1; wv < 8; wv++) {
            float4 cw = cbase[wv];
            float b1 = cw.x, b2 = cw.y;
            int   k1 = __float_as_int(cw.z), k2 = __float_as_int(cw.w);
            if (b1 > best1) {
                // new top is b1; second = max(best1, b2), ties -> best1 (lower idx)
                if (b2 > best1) { best2 = b2; j2 = k2; }
                else            { best2 = best1; j2 = j1; }
                best1 = b1; j1 = k1;
            } else if (b1 > best2) {
                best2 = b1; j2 = k1;
            }
        }
        int t = row0 + tid;
        float ed = __expf(best2 - best1);
        float p1 = 1.0f / (1.0f + ed);
        float p2 = ed / (1.0f + ed);
        g_top[t]        = j1;
        g_top[NTOK + t] = j2;
        out_probs[2 * t]     = p1;
        out_probs[2 * t + 1] = p2;
        out_idx[2 * t]       = (float)j1;
        out_idx[2 * t + 1]   = (float)j2;
    }
}

// ---------------------------------------------------------------------------
// Kernel 2: rank/capacity. 128 CTAs: bid>>1 = expert, bid&1 = stream.
// Stream-1 CTAs first count stream-0 matches (carry), then scan their stream.
// ---------------------------------------------------------------------------
__global__ __launch_bounds__(1024) void rank_kernel(
    float* __restrict__ out_mask, float* __restrict__ out_probs,
    float* __restrict__ out_rank)
{
    const int e    = blockIdx.x >> 1;
    const int s    = blockIdx.x & 1;
    const int tid  = threadIdx.x;
    const int lane = tid & 31;
    const int wid  = tid >> 5;

    __shared__ int wsum[32];
    __shared__ int stotal;

    int carry = 0;
    if (s == 1) {
        const int4* p0 = reinterpret_cast<const int4*>(g_top);
        int cnt = 0;
#pragma unroll
        for (int i = 0; i < 8; i++) {
            int4 v = p0[i * 1024 + tid];
            cnt += (v.x == e) + (v.y == e) + (v.z == e) + (v.w == e);
        }
#pragma unroll
        for (int o = 16; o > 0; o >>= 1) cnt += __shfl_down_sync(0xffffffffu, cnt, o);
        if (lane == 0) wsum[wid] = cnt;
        __syncthreads();
        if (tid < 32) {
            int c2 = wsum[lane];
#pragma unroll
            for (int o = 16; o > 0; o >>= 1) c2 += __shfl_down_sync(0xffffffffu, c2, o);
            if (lane == 0) stotal = c2;
        }
        __syncthreads();
        carry = stotal;
    }

    const int4* p = reinterpret_cast<const int4*>(g_top + s * NTOK);
#pragma unroll 1
    for (int c = 0; c < NTOK / 4096; c++) {
        int4 v = p[c * 1024 + tid];
        int m0 = (v.x == e), m1 = (v.y == e), m2 = (v.z == e), m3 = (v.w == e);
        int cs = m0 + m1 + m2 + m3;

        int inc = cs;
#pragma unroll
        for (int o = 1; o < 32; o <<= 1) {
            int t2 = __shfl_up_sync(0xffffffffu, inc, o);
            if (lane >= o) inc += t2;
        }
        if (lane == 31) wsum[wid] = inc;
        __syncthreads();
        if (wid == 0) {
            int wv = wsum[lane];
            int winc = wv;
#pragma unroll
            for (int o = 1; o < 32; o <<= 1) {
                int t2 = __shfl_up_sync(0xffffffffu, winc, o);
                if (lane >= o) winc += t2;
            }
            wsum[lane] = winc - wv;
            if (lane == 31) stotal = winc;
        }
        __syncthreads();

        int r  = carry + wsum[wid] + (inc - cs);
        int i0 = (c * 1024 + tid) * 4;

        if (m0) {
            int oi = (i0 + 0) * 2 + s;
            out_rank[oi] = (float)r;
            if (r < CAPV) out_mask[(size_t)oi * NEXP + e] = 1.0f;
            else out_probs[oi] = 0.0f;
            r++;
        }
        if (m1) {
            int oi = (i0 + 1) * 2 + s;
            out_rank[oi] = (float)r;
            if (r < CAPV) out_mask[(size_t)oi * NEXP + e] = 1.0f;
            else out_probs[oi] = 0.0f;
            r++;
        }
        if (m2) {
            int oi = (i0 + 2) * 2 + s;
            out_rank[oi] = (float)r;
            if (r < CAPV) out_mask[(size_t)oi * NEXP + e] = 1.0f;
            else out_probs[oi] = 0.0f;
            r++;
        }
        if (m3) {
            int oi = (i0 + 3) * 2 + s;
            out_rank[oi] = (float)r;
            if (r < CAPV) out_mask[(size_t)oi * NEXP + e] = 1.0f;
            else out_probs[oi] = 0.0f;
            r++;
        }
        carry += stotal;
        __syncthreads();
    }
}

// ---------------------------------------------------------------------------
extern "C" void kernel_launch(void* const* d_in, const int* in_sizes, int n_in,
                              void* d_out, int out_size)
{
    const float* x = (const float*)d_in[0];
    const float* w = (const float*)d_in[1];

    float* out       = (float*)d_out;
    float* out_mask  = out;                                   // N*2*64
    float* out_probs = out + (size_t)NTOK * 2 * NEXP;         // N*2
    float* out_idx   = out_probs + NTOK * 2;                  // N*2
    float* out_rank  = out_idx + NTOK * 2;                    // N*2

    cudaMemsetAsync(out_mask, 0, (size_t)NTOK * 2 * NEXP * sizeof(float));
    gemm_top2_kernel<<<NTOK / BM, THREADS>>>(x, w, out_probs, out_idx);
    rank_kernel<<<2 * NEXP, 1024>>>(out_mask, out_probs, out_rank);
}